// round 4
// baseline (speedup 1.0000x reference)
#include <cuda_runtime.h>

// GeneralMechanismODE — pure single-touch stream (96 B in, 32 B out per row).
// R4: persistent grid-stride kernel at exact full-machine residency.
//   - grid = #SMs * 8 blocks of 256 => 64 warps/SM resident, one wave total
//   - each thread loops over rows; loop body keeps 4 front-batched LDG.128
//   - ptxas pipelines next-iter loads against current-iter stores (MLP up
//     with NO loss of warp count — the fix for R2's occupancy regression)
//   - must stay <= 32 regs for 64 warps/SM (R1/R3 body was 26)

__global__ __launch_bounds__(256) void ode_kernel4(
    const float4* __restrict__ y,    // 2*B float4
    const float4* __restrict__ kf,   // B float4
    const float4* __restrict__ kr,   // B float4
    float4* __restrict__ out,        // 2*B float4
    int B)
{
    int stride = gridDim.x * blockDim.x;
    for (int b = blockIdx.x * blockDim.x + threadIdx.x; b < B; b += stride) {
        // 4 independent 128-bit streaming loads, front-batched.
        float4 ylo = __ldcs(&y[2 * b + 0]);   // y0..y3
        float4 yhi = __ldcs(&y[2 * b + 1]);   // y4..y7
        float4 f   = __ldcs(&kf[b]);
        float4 r   = __ldcs(&kr[b]);

        float v0 = f.x * ylo.x * yhi.x - r.x * ylo.y;          // kf0*E*A  - kr0*EA
        float v1 = f.y * ylo.y * yhi.y - r.y * ylo.w;          // kf1*EA*B - kr1*EAB
        float v2 = f.z * ylo.w         - r.z * ylo.z * yhi.z;  // kf2*EAB  - kr2*EQ*P
        float v3 = f.w * ylo.z         - r.w * ylo.x * yhi.w;  // kf3*EQ   - kr3*E*Q

        float4 olo, ohi;
        olo.x = v3 - v0;   // dE
        olo.y = v0 - v1;   // dEA
        olo.z = v2 - v3;   // dEQ
        olo.w = v1 - v2;   // dEAB
        ohi.x = -v0;       // dA
        ohi.y = -v1;       // dB
        ohi.z = v2;        // dP
        ohi.w = v3;        // dQ

        __stcs(&out[2 * b + 0], olo);
        __stcs(&out[2 * b + 1], ohi);
    }
}

extern "C" void kernel_launch(void* const* d_in, const int* in_sizes, int n_in,
                              void* d_out, int out_size)
{
    // metadata order: t (1), y (B*8), forward_rates (B*4), reverse_rates (B*4)
    const float4* y  = (const float4*)d_in[1];
    const float4* kf = (const float4*)d_in[2];
    const float4* kr = (const float4*)d_in[3];
    float4* out = (float4*)d_out;

    int B = in_sizes[1] / 8;
    int threads = 256;

    // Full-machine persistent grid: 8 blocks of 256 per SM = 64 warps/SM.
    int dev = 0, sms = 148;
    cudaGetDevice(&dev);
    cudaDeviceGetAttribute(&sms, cudaDevAttrMultiProcessorCount, dev);
    int blocks = sms * 8;
    int needed = (B + threads - 1) / threads;
    if (blocks > needed) blocks = needed;

    ode_kernel4<<<blocks, threads>>>(y, kf, kr, out, B);
}

// round 5
// speedup vs baseline: 1.2100x; 1.2100x over previous
#include <cuda_runtime.h>

// GeneralMechanismODE — pure single-touch stream (96 B in, 32 B out per row).
// R5: R3 body unchanged (the winning structure: no loop-carried hazards,
// 4 front-batched LDG.128 per thread, 26 regs, CTA-churn-driven MLP),
// block size 128 for finer CTA churn granularity (16 CTAs/SM instead of 8,
// same 64 resident warps/SM). R4 proved churn — not occupancy, not
// per-thread MLP — is what keeps the DRAM queues full.

__global__ __launch_bounds__(128) void ode_kernel5(
    const float4* __restrict__ y,    // 2*B float4
    const float4* __restrict__ kf,   // B float4
    const float4* __restrict__ kr,   // B float4
    float4* __restrict__ out,        // 2*B float4
    int B)
{
    int b = blockIdx.x * blockDim.x + threadIdx.x;
    if (b >= B) return;

    // 4 independent 128-bit streaming loads, front-batched.
    float4 ylo = __ldcs(&y[2 * b + 0]);   // y0..y3
    float4 yhi = __ldcs(&y[2 * b + 1]);   // y4..y7
    float4 f   = __ldcs(&kf[b]);
    float4 r   = __ldcs(&kr[b]);

    float v0 = f.x * ylo.x * yhi.x - r.x * ylo.y;          // kf0*E*A  - kr0*EA
    float v1 = f.y * ylo.y * yhi.y - r.y * ylo.w;          // kf1*EA*B - kr1*EAB
    float v2 = f.z * ylo.w         - r.z * ylo.z * yhi.z;  // kf2*EAB  - kr2*EQ*P
    float v3 = f.w * ylo.z         - r.w * ylo.x * yhi.w;  // kf3*EQ   - kr3*E*Q

    float4 olo, ohi;
    olo.x = v3 - v0;   // dE
    olo.y = v0 - v1;   // dEA
    olo.z = v2 - v3;   // dEQ
    olo.w = v1 - v2;   // dEAB
    ohi.x = -v0;       // dA
    ohi.y = -v1;       // dB
    ohi.z = v2;        // dP
    ohi.w = v3;        // dQ

    __stcs(&out[2 * b + 0], olo);
    __stcs(&out[2 * b + 1], ohi);
}

extern "C" void kernel_launch(void* const* d_in, const int* in_sizes, int n_in,
                              void* d_out, int out_size)
{
    // metadata order: t (1), y (B*8), forward_rates (B*4), reverse_rates (B*4)
    const float4* y  = (const float4*)d_in[1];
    const float4* kf = (const float4*)d_in[2];
    const float4* kr = (const float4*)d_in[3];
    float4* out = (float4*)d_out;

    int B = in_sizes[1] / 8;
    int threads = 128;
    int blocks = (B + threads - 1) / threads;
    ode_kernel5<<<blocks, threads>>>(y, kf, kr, out, B);
}